// round 1
// baseline (speedup 1.0000x reference)
#include <cuda_runtime.h>
#include <cuda_bf16.h>
#include <cstdint>
#include <cstddef>

// ---------------------------------------------------------------------------
// MixHop (dense adjacency) — fp32 baseline
//   N=8192, IN=128, H=512, OUT=256, HOPS=2
//   out = ( BNReLU(mixhop1(x)) -> mixhop2 ) @ Wf + bf
// All heavy work in a single tiled SGEMM (128x128x16, 8x8/thread).
// ---------------------------------------------------------------------------

#define NNODE 8192
#define IN_DIM 128
#define HID 512
#define OUTD 256
#define H3 1536   // 3*HID
#define O3 768    // 3*OUTD
#define BN_EPS 1e-5f

// Scratch (allocation-free: device globals)
__device__ float g_T1[(size_t)NNODE * HID];
__device__ float g_T2[(size_t)NNODE * HID];
__device__ float g_T3[(size_t)NNODE * HID];
__device__ float g_h1[(size_t)NNODE * H3];
__device__ float g_U1[(size_t)NNODE * OUTD];
__device__ float g_U2[(size_t)NNODE * OUTD];
__device__ float g_U3[(size_t)NNODE * OUTD];
__device__ float g_h2[(size_t)NNODE * O3];
__device__ double g_sum[H3];
__device__ double g_sq[H3];

// ---------------------------------------------------------------------------
// SGEMM: C[M,N] = A[M,K] @ B[K,N] (+ bias[n]), row-major, arbitrary ld.
// Requires: M%128==0, N%128==0, K%16==0, lda/ldb/ldc%4==0 (true for all calls).
// grid = (N/128, M/128), block = 256 threads.
// ---------------------------------------------------------------------------
__global__ __launch_bounds__(256, 2)
void sgemm128(const float* __restrict__ A, int lda,
              const float* __restrict__ B, int ldb,
              float* __restrict__ C, int ldc,
              int K, const float* __restrict__ bias)
{
    __shared__ float As[2][16][132];   // transposed A tile, padded
    __shared__ float Bs[2][16][128];

    const int tid = threadIdx.x;
    const int bx = blockIdx.x, by = blockIdx.y;

    const float* Abase = A + (size_t)by * 128 * lda;
    const float* Bbase = B + (size_t)bx * 128;

    // A-tile loader mapping: 512 float4 per tile, 2 per thread
    const int arow = tid >> 2;            // 0..63
    const int acol = (tid & 3) << 2;      // 0,4,8,12
    // B-tile loader mapping
    const int brow = tid >> 5;            // 0..7
    const int bcol = (tid & 31) << 2;     // 0..124

    // compute mapping: 16x16 threads of 8x8
    const int ty = (tid >> 4) << 3;       // row offset 0..120
    const int tx = (tid & 15) << 3;       // col offset 0..120

    float acc[8][8];
    #pragma unroll
    for (int i = 0; i < 8; i++)
        #pragma unroll
        for (int j = 0; j < 8; j++) acc[i][j] = 0.0f;

    float4 pa0, pa1, pb0, pb1;

    // prologue: load tile 0
    {
        const int k0 = 0;
        pa0 = *(const float4*)(Abase + (size_t)arow * lda + k0 + acol);
        pa1 = *(const float4*)(Abase + (size_t)(arow + 64) * lda + k0 + acol);
        pb0 = *(const float4*)(Bbase + (size_t)(k0 + brow) * ldb + bcol);
        pb1 = *(const float4*)(Bbase + (size_t)(k0 + brow + 8) * ldb + bcol);
        As[0][acol + 0][arow] = pa0.x;
        As[0][acol + 1][arow] = pa0.y;
        As[0][acol + 2][arow] = pa0.z;
        As[0][acol + 3][arow] = pa0.w;
        As[0][acol + 0][arow + 64] = pa1.x;
        As[0][acol + 1][arow + 64] = pa1.y;
        As[0][acol + 2][arow + 64] = pa1.z;
        As[0][acol + 3][arow + 64] = pa1.w;
        *(float4*)&Bs[0][brow][bcol] = pb0;
        *(float4*)&Bs[0][brow + 8][bcol] = pb1;
    }
    __syncthreads();

    const int nk = K >> 4;
    for (int t = 0; t < nk; t++) {
        const int buf = t & 1;
        const bool more = (t + 1 < nk);
        if (more) {
            const int k0 = (t + 1) << 4;
            pa0 = *(const float4*)(Abase + (size_t)arow * lda + k0 + acol);
            pa1 = *(const float4*)(Abase + (size_t)(arow + 64) * lda + k0 + acol);
            pb0 = *(const float4*)(Bbase + (size_t)(k0 + brow) * ldb + bcol);
            pb1 = *(const float4*)(Bbase + (size_t)(k0 + brow + 8) * ldb + bcol);
        }
        #pragma unroll
        for (int kk = 0; kk < 16; kk++) {
            float4 a0 = *(const float4*)&As[buf][kk][ty];
            float4 a1 = *(const float4*)&As[buf][kk][ty + 4];
            float4 b0 = *(const float4*)&Bs[buf][kk][tx];
            float4 b1 = *(const float4*)&Bs[buf][kk][tx + 4];
            float ar[8] = {a0.x, a0.y, a0.z, a0.w, a1.x, a1.y, a1.z, a1.w};
            float br[8] = {b0.x, b0.y, b0.z, b0.w, b1.x, b1.y, b1.z, b1.w};
            #pragma unroll
            for (int i = 0; i < 8; i++)
                #pragma unroll
                for (int j = 0; j < 8; j++)
                    acc[i][j] = fmaf(ar[i], br[j], acc[i][j]);
        }
        if (more) {
            const int nb = buf ^ 1;
            As[nb][acol + 0][arow] = pa0.x;
            As[nb][acol + 1][arow] = pa0.y;
            As[nb][acol + 2][arow] = pa0.z;
            As[nb][acol + 3][arow] = pa0.w;
            As[nb][acol + 0][arow + 64] = pa1.x;
            As[nb][acol + 1][arow + 64] = pa1.y;
            As[nb][acol + 2][arow + 64] = pa1.z;
            As[nb][acol + 3][arow + 64] = pa1.w;
            *(float4*)&Bs[nb][brow][bcol] = pb0;
            *(float4*)&Bs[nb][brow + 8][bcol] = pb1;
        }
        __syncthreads();
    }

    // epilogue: optional bias, store
    float bv[8];
    if (bias != nullptr) {
        #pragma unroll
        for (int j = 0; j < 8; j++) bv[j] = bias[bx * 128 + tx + j];
    } else {
        #pragma unroll
        for (int j = 0; j < 8; j++) bv[j] = 0.0f;
    }
    float* Cb = C + (size_t)(by * 128 + ty) * ldc + bx * 128 + tx;
    #pragma unroll
    for (int i = 0; i < 8; i++) {
        float4 c0 = make_float4(acc[i][0] + bv[0], acc[i][1] + bv[1],
                                acc[i][2] + bv[2], acc[i][3] + bv[3]);
        float4 c1 = make_float4(acc[i][4] + bv[4], acc[i][5] + bv[5],
                                acc[i][6] + bv[6], acc[i][7] + bv[7]);
        *(float4*)(Cb + (size_t)i * ldc) = c0;
        *(float4*)(Cb + (size_t)i * ldc + 4) = c1;
    }
}

// ---------------------------------------------------------------------------
// BatchNorm (training-mode stats) + ReLU on g_h1 [NNODE, H3], in place
// ---------------------------------------------------------------------------
__global__ void zero_stats()
{
    int i = blockIdx.x * blockDim.x + threadIdx.x;
    if (i < H3) { g_sum[i] = 0.0; g_sq[i] = 0.0; }
}

__global__ void bn_stats(const float* __restrict__ h)
{
    const int col = blockIdx.x * 256 + threadIdx.x;   // 6 blocks in x
    const int r0 = blockIdx.y * 256;                  // 32 chunks in y
    double ls = 0.0, lq = 0.0;
    #pragma unroll 4
    for (int r = r0; r < r0 + 256; r++) {
        float v = h[(size_t)r * H3 + col];
        ls += (double)v;
        lq += (double)v * (double)v;
    }
    atomicAdd(&g_sum[col], ls);
    atomicAdd(&g_sq[col], lq);
}

__global__ void bn_apply(float* __restrict__ h,
                         const float* __restrict__ gamma,
                         const float* __restrict__ beta)
{
    size_t i = (size_t)blockIdx.x * blockDim.x + threadIdx.x;
    if (i >= (size_t)NNODE * H3) return;
    int col = (int)(i % H3);
    double mu = g_sum[col] / (double)NNODE;
    double var = g_sq[col] / (double)NNODE - mu * mu;
    float rstd = rsqrtf((float)var + BN_EPS);
    float v = (h[i] - (float)mu) * rstd * gamma[col] + beta[col];
    h[i] = v > 0.0f ? v : 0.0f;
}

// ---------------------------------------------------------------------------
// Launch orchestration
// ---------------------------------------------------------------------------
extern "C" void kernel_launch(void* const* d_in, const int* in_sizes, int n_in,
                              void* d_out, int out_size)
{
    const float* x     = (const float*)d_in[0];   // [8192,128]
    const float* adj   = (const float*)d_in[1];   // [8192,8192]
    const float* W1    = (const float*)d_in[2];   // [3,128,512]
    const float* b1    = (const float*)d_in[3];   // [3,512]
    const float* W2    = (const float*)d_in[4];   // [3,1536,256]
    const float* b2    = (const float*)d_in[5];   // [3,256]
    const float* gamma = (const float*)d_in[6];   // [1536]
    const float* beta  = (const float*)d_in[7];   // [1536]
    const float* Wf    = (const float*)d_in[8];   // [768,256]
    const float* bf    = (const float*)d_in[9];   // [256]
    float* out = (float*)d_out;                   // [8192,256]

    float *T1, *T2, *T3, *h1, *U1, *U2, *U3, *h2;
    cudaGetSymbolAddress((void**)&T1, g_T1);
    cudaGetSymbolAddress((void**)&T2, g_T2);
    cudaGetSymbolAddress((void**)&T3, g_T3);
    cudaGetSymbolAddress((void**)&h1, g_h1);
    cudaGetSymbolAddress((void**)&U1, g_U1);
    cudaGetSymbolAddress((void**)&U2, g_U2);
    cudaGetSymbolAddress((void**)&U3, g_U3);
    cudaGetSymbolAddress((void**)&h2, g_h2);

    const dim3 blk(256);
    const dim3 gridH(HID / 128, NNODE / 128);    // N=512
    const dim3 gridO(OUTD / 128, NNODE / 128);   // N=256

    // ---- Layer 1: x @ W1[j] + b1[j] ----
    sgemm128<<<gridH, blk>>>(x, IN_DIM, W1,                 HID, h1,       H3, IN_DIM, b1);
    sgemm128<<<gridH, blk>>>(x, IN_DIM, W1 + 1 * IN_DIM * HID, HID, T1,   HID, IN_DIM, b1 + HID);
    sgemm128<<<gridH, blk>>>(x, IN_DIM, W1 + 2 * IN_DIM * HID, HID, T2,   HID, IN_DIM, b1 + 2 * HID);
    // adjacency propagation
    sgemm128<<<gridH, blk>>>(adj, NNODE, T1, HID, h1 + HID,     H3, NNODE, nullptr);  // hop1
    sgemm128<<<gridH, blk>>>(adj, NNODE, T2, HID, T3,           HID, NNODE, nullptr); // hop2 step1
    sgemm128<<<gridH, blk>>>(adj, NNODE, T3, HID, h1 + 2 * HID, H3, NNODE, nullptr);  // hop2 step2

    // ---- BatchNorm + ReLU (in place on h1) ----
    zero_stats<<<(H3 + 255) / 256, 256>>>();
    bn_stats<<<dim3(H3 / 256, NNODE / 256), 256>>>(h1);
    {
        size_t tot = (size_t)NNODE * H3;
        bn_apply<<<(unsigned)((tot + 255) / 256), 256>>>(h1, gamma, beta);
    }

    // ---- Layer 2: h1 @ W2[j] + b2[j] ----
    sgemm128<<<gridO, blk>>>(h1, H3, W2,                  OUTD, h2,        O3, H3, b2);
    sgemm128<<<gridO, blk>>>(h1, H3, W2 + 1 * H3 * OUTD,  OUTD, U1,      OUTD, H3, b2 + OUTD);
    sgemm128<<<gridO, blk>>>(h1, H3, W2 + 2 * H3 * OUTD,  OUTD, U2,      OUTD, H3, b2 + 2 * OUTD);
    // adjacency propagation
    sgemm128<<<gridO, blk>>>(adj, NNODE, U1, OUTD, h2 + OUTD,     O3, NNODE, nullptr);
    sgemm128<<<gridO, blk>>>(adj, NNODE, U2, OUTD, U3,          OUTD, NNODE, nullptr);
    sgemm128<<<gridO, blk>>>(adj, NNODE, U3, OUTD, h2 + 2 * OUTD, O3, NNODE, nullptr);

    // ---- Final projection: out = h2 @ Wf + bf ----
    sgemm128<<<gridO, blk>>>(h2, O3, Wf, OUTD, out, OUTD, O3, bf);
}

// round 3
// speedup vs baseline: 2.4052x; 2.4052x over previous
#include <cuda_runtime.h>
#include <cuda_bf16.h>
#include <cstdint>
#include <cstddef>

#define NNODE 8192
#define IN_DIM 128
#define HID 512
#define OUTD 256
#define H3 1536
#define O3 768
#define BN_EPS 1e-5f

// ---------------------------------------------------------------------------
// Device scratch (allocation-free)
// ---------------------------------------------------------------------------
__device__ __nv_bfloat16 g_adj_h[(size_t)NNODE * NNODE];
__device__ __nv_bfloat16 g_adj_l[(size_t)NNODE * NNODE];
__device__ __nv_bfloat16 g_x_h[(size_t)NNODE * IN_DIM];
__device__ __nv_bfloat16 g_x_l[(size_t)NNODE * IN_DIM];
__device__ __nv_bfloat16 g_W1t_h[3 * HID * IN_DIM];
__device__ __nv_bfloat16 g_W1t_l[3 * HID * IN_DIM];
__device__ __nv_bfloat16 g_W2t_h[3 * OUTD * H3];
__device__ __nv_bfloat16 g_W2t_l[3 * OUTD * H3];
__device__ __nv_bfloat16 g_Wft_h[OUTD * O3];
__device__ __nv_bfloat16 g_Wft_l[OUTD * O3];
__device__ __nv_bfloat16 g_T1t_h[(size_t)HID * NNODE];
__device__ __nv_bfloat16 g_T1t_l[(size_t)HID * NNODE];
__device__ __nv_bfloat16 g_T2t_h[(size_t)HID * NNODE];
__device__ __nv_bfloat16 g_T2t_l[(size_t)HID * NNODE];
__device__ __nv_bfloat16 g_T3t_h[(size_t)HID * NNODE];
__device__ __nv_bfloat16 g_T3t_l[(size_t)HID * NNODE];
__device__ __nv_bfloat16 g_U12t_h[(size_t)HID * NNODE];   // rows 0..255=U1^T, 256..511=U2^T
__device__ __nv_bfloat16 g_U12t_l[(size_t)HID * NNODE];
__device__ __nv_bfloat16 g_U3t_h[(size_t)OUTD * NNODE];
__device__ __nv_bfloat16 g_U3t_l[(size_t)OUTD * NNODE];
__device__ float g_h1[(size_t)NNODE * H3];
__device__ __nv_bfloat16 g_h1_h[(size_t)NNODE * H3];
__device__ __nv_bfloat16 g_h1_l[(size_t)NNODE * H3];
__device__ float g_h2[(size_t)NNODE * O3];
__device__ __nv_bfloat16 g_h2_h[(size_t)NNODE * O3];
__device__ __nv_bfloat16 g_h2_l[(size_t)NNODE * O3];
__device__ double g_sum[H3];
__device__ double g_sq[H3];

// ---------------------------------------------------------------------------
// PTX helpers (Ampere-era: compile fine at compute_100)
// ---------------------------------------------------------------------------
__device__ __forceinline__ uint32_t smem_u32(const void* p) {
    uint32_t a;
    asm("{ .reg .u64 t; cvta.to.shared.u64 t, %1; cvt.u32.u64 %0, t; }"
        : "=r"(a) : "l"(p));
    return a;
}

__device__ __forceinline__ void cpa16(uint32_t dst, const void* src) {
    asm volatile("cp.async.cg.shared.global [%0], [%1], 16;" :: "r"(dst), "l"(src));
}
#define CP_COMMIT() asm volatile("cp.async.commit_group;" ::: "memory")
#define CP_WAIT(n)  asm volatile("cp.async.wait_group %0;" :: "n"(n) : "memory")

__device__ __forceinline__ void ldm_x4(uint32_t* r, uint32_t a) {
    asm volatile("ldmatrix.sync.aligned.m8n8.x4.shared.b16 {%0,%1,%2,%3}, [%4];"
        : "=r"(r[0]), "=r"(r[1]), "=r"(r[2]), "=r"(r[3]) : "r"(a));
}

__device__ __forceinline__ void mma_bf16(float* c, const uint32_t* a, const uint32_t* b) {
    asm volatile(
        "mma.sync.aligned.m16n8k16.row.col.f32.bf16.bf16.f32 "
        "{%0,%1,%2,%3}, {%4,%5,%6,%7}, {%8,%9}, {%0,%1,%2,%3};"
        : "+f"(c[0]), "+f"(c[1]), "+f"(c[2]), "+f"(c[3])
        : "r"(a[0]), "r"(a[1]), "r"(a[2]), "r"(a[3]), "r"(b[0]), "r"(b[1]));
}

// smem tile: 128 rows x 32 bf16 (64B/row); XOR swizzle keeps ldmatrix
// column reads (8 rows @ same 16B chunk) conflict-free within 128B windows.
__device__ __forceinline__ uint32_t sw_off(int r, int c) {
    return (uint32_t)(r * 64 + ((c ^ ((r >> 1) & 3)) << 4));
}

// ---------------------------------------------------------------------------
// Split-precision bf16 GEMM via mma.sync:
//   C[M,N] = A[M,K] @ B^T  (B stored transposed [N,K] row-major)
//   D += Ah*Bh + Ah*Bl + Al*Bh  (fp32 accum)
// CTA tile 128x128x32, 256 threads (8 warps, 2x4), warp tile 64x32.
// Epilogue: gcol < splitcol -> fp32 C (+bias); else -> transposed bf16 hi/lo.
// ---------------------------------------------------------------------------
__global__ void __launch_bounds__(256, 1)
gemm_mma(const __nv_bfloat16* __restrict__ Ah, const __nv_bfloat16* __restrict__ Al,
         const __nv_bfloat16* __restrict__ Bh, const __nv_bfloat16* __restrict__ Bl,
         int K,
         float* __restrict__ Cf, int ldc,
         __nv_bfloat16* __restrict__ Th, __nv_bfloat16* __restrict__ Tl,
         int splitcol, const float* __restrict__ bias)
{
    constexpr int SUB = 128 * 32 * 2;   // bytes per sub-tile (Ah/Al/Bh/Bl)
    constexpr int STG = 4 * SUB;        // 32 KB per stage
    extern __shared__ char smem[];
    const uint32_t sb = smem_u32(smem);

    const int tid = threadIdx.x;
    const int bx = blockIdx.x, by = blockIdx.y;

    // ---- loader mapping: thread -> (row, 2 chunks of 16B) ----
    const int lr = tid >> 1;
    const int lc = (tid & 1) * 2;
    const __nv_bfloat16* pAh = Ah + (size_t)(by * 128 + lr) * K + lc * 8;
    const __nv_bfloat16* pAl = Al + (size_t)(by * 128 + lr) * K + lc * 8;
    const __nv_bfloat16* pBh = Bh + (size_t)(bx * 128 + lr) * K + lc * 8;
    const __nv_bfloat16* pBl = Bl + (size_t)(bx * 128 + lr) * K + lc * 8;
    const uint32_t d0 = sb + sw_off(lr, lc);
    const uint32_t d1 = sb + sw_off(lr, lc + 1);

    // ---- compute mapping ----
    const int w = tid >> 5, l = tid & 31;
    const int RM = (w >> 2) * 64;       // warp row base
    const int CN = (w & 3) * 32;        // warp col base

    // A ldmatrix: tile mt, kstep ks -> row RM+mt*16+(l&15), chunk ks*2+(l>>4)
    uint32_t aoff[4][2];
    #pragma unroll
    for (int mt = 0; mt < 4; mt++) {
        const int r = RM + mt * 16 + (l & 15);
        #pragma unroll
        for (int ks = 0; ks < 2; ks++)
            aoff[mt][ks] = sw_off(r, ks * 2 + (l >> 4));
    }
    // B ldmatrix (x4 covers 2 n-tiles): pair np, ks ->
    //   row CN+np*16+((l>>4)<<3)+(l&7), chunk ks*2+((l>>3)&1)
    uint32_t boff[2][2];
    #pragma unroll
    for (int np = 0; np < 2; np++) {
        const int r = CN + np * 16 + ((l >> 4) << 3) + (l & 7);
        #pragma unroll
        for (int ks = 0; ks < 2; ks++)
            boff[np][ks] = sw_off(r, ks * 2 + ((l >> 3) & 1));
    }

    float acc[4][4][4];
    #pragma unroll
    for (int mt = 0; mt < 4; mt++)
        #pragma unroll
        for (int nt = 0; nt < 4; nt++)
            #pragma unroll
            for (int k = 0; k < 4; k++) acc[mt][nt][k] = 0.0f;

    const int nk = K >> 5;

    // prologue: stage 0
    {
        cpa16(d0, pAh);            cpa16(d1, pAh + 8);
        cpa16(d0 + SUB, pAl);      cpa16(d1 + SUB, pAl + 8);
        cpa16(d0 + 2 * SUB, pBh);  cpa16(d1 + 2 * SUB, pBh + 8);
        cpa16(d0 + 3 * SUB, pBl);  cpa16(d1 + 3 * SUB, pBl + 8);
        CP_COMMIT();
    }

    for (int c = 0; c < nk; c++) {
        if (c + 1 < nk) {
            const int k0 = (c + 1) << 5;
            const uint32_t ds = ((c + 1) & 1) * STG;
            cpa16(d0 + ds, pAh + k0);            cpa16(d1 + ds, pAh + k0 + 8);
            cpa16(d0 + ds + SUB, pAl + k0);      cpa16(d1 + ds + SUB, pAl + k0 + 8);
            cpa16(d0 + ds + 2 * SUB, pBh + k0);  cpa16(d1 + ds + 2 * SUB, pBh + k0 + 8);
            cpa16(d0 + ds + 3 * SUB, pBl + k0);  cpa16(d1 + ds + 3 * SUB, pBl + k0 + 8);
            CP_COMMIT();
            CP_WAIT(1);
        } else {
            CP_WAIT(0);
        }
        __syncthreads();

        const uint32_t sbase = sb + (c & 1) * STG;
        #pragma unroll
        for (int ks = 0; ks < 2; ks++) {
            uint32_t ahf[4][4], alf[4][4], bhf[2][4], blf[2][4];
            #pragma unroll
            for (int mt = 0; mt < 4; mt++) {
                ldm_x4(ahf[mt], sbase + aoff[mt][ks]);
                ldm_x4(alf[mt], sbase + SUB + aoff[mt][ks]);
            }
            #pragma unroll
            for (int np = 0; np < 2; np++) {
                ldm_x4(bhf[np], sbase + 2 * SUB + boff[np][ks]);
                ldm_x4(blf[np], sbase + 3 * SUB + boff[np][ks]);
            }
            #pragma unroll
            for (int mt = 0; mt < 4; mt++)
                #pragma unroll
                for (int nt = 0; nt < 4; nt++) {
                    const uint32_t* bh = &bhf[nt >> 1][(nt & 1) * 2];
                    const uint32_t* bl = &blf[nt >> 1][(nt & 1) * 2];
                    mma_bf16(acc[mt][nt], ahf[mt], bh);
                    mma_bf16(acc[mt][nt], ahf[mt], bl);
                    mma_bf16(acc[mt][nt], alf[mt], bh);
                }
        }
        __syncthreads();
    }

    // ---- epilogue ----
    #pragma unroll
    for (int mt = 0; mt < 4; mt++) {
        const int r0 = by * 128 + RM + mt * 16 + (l >> 2);
        #pragma unroll
        for (int nt = 0; nt < 4; nt++) {
            const int gc = bx * 128 + CN + nt * 8 + ((l & 3) << 1);
            float v0 = acc[mt][nt][0], v1 = acc[mt][nt][1];
            float v2 = acc[mt][nt][2], v3 = acc[mt][nt][3];
            if (bias) {
                const float bb0 = __ldg(bias + gc), bb1 = __ldg(bias + gc + 1);
                v0 += bb0; v1 += bb1; v2 += bb0; v3 += bb1;
            }
            if (gc < splitcol) {
                *(float2*)&Cf[(size_t)r0 * ldc + gc] = make_float2(v0, v1);
                *(float2*)&Cf[(size_t)(r0 + 8) * ldc + gc] = make_float2(v2, v3);
            } else {
                const size_t o0 = (size_t)(gc - splitcol) * NNODE;
                const size_t o1 = o0 + NNODE;
                float vv[4] = {v0, v1, v2, v3};
                size_t oo[4] = {o0 + r0, o1 + r0, o0 + r0 + 8, o1 + r0 + 8};
                #pragma unroll
                for (int q = 0; q < 4; q++) {
                    const __nv_bfloat16 h = __float2bfloat16(vv[q]);
                    Th[oo[q]] = h;
                    Tl[oo[q]] = __float2bfloat16(vv[q] - __bfloat162float(h));
                }
            }
        }
    }
}

// ---------------------------------------------------------------------------
// fp32 -> (bf16 hi, bf16 lo) converters
// ---------------------------------------------------------------------------
__global__ void cvt_split(const float* __restrict__ s,
                          __nv_bfloat16* __restrict__ h,
                          __nv_bfloat16* __restrict__ l, size_t n)
{
    const size_t i = ((size_t)blockIdx.x * 256 + threadIdx.x) * 4;
    if (i >= n) return;
    const float4 v = *(const float4*)(s + i);
    float a[4] = {v.x, v.y, v.z, v.w};
    __nv_bfloat16 hh[4], ll[4];
    #pragma unroll
    for (int k = 0; k < 4; k++) {
        hh[k] = __float2bfloat16(a[k]);
        ll[k] = __float2bfloat16(a[k] - __bfloat162float(hh[k]));
    }
    ((__nv_bfloat162*)(h + i))[0] = __halves2bfloat162(hh[0], hh[1]);
    ((__nv_bfloat162*)(h + i))[1] = __halves2bfloat162(hh[2], hh[3]);
    ((__nv_bfloat162*)(l + i))[0] = __halves2bfloat162(ll[0], ll[1]);
    ((__nv_bfloat162*)(l + i))[1] = __halves2bfloat162(ll[2], ll[3]);
}

// [R,C] fp32 -> [C,R] bf16 hi/lo
__global__ void cvt_split_tr(const float* __restrict__ s,
                             __nv_bfloat16* __restrict__ dh,
                             __nv_bfloat16* __restrict__ dl, int R, int C)
{
    __shared__ float t[32][33];
    const int c0 = blockIdx.x * 32, r0 = blockIdx.y * 32;
    const int tx = threadIdx.x, ty = threadIdx.y;
    #pragma unroll
    for (int j = 0; j < 4; j++)
        t[ty + 8 * j][tx] = s[(size_t)(r0 + ty + 8 * j) * C + c0 + tx];
    __syncthreads();
    #pragma unroll
    for (int j = 0; j < 4; j++) {
        const float v = t[tx][ty + 8 * j];
        const __nv_bfloat16 h = __float2bfloat16(v);
        const __nv_bfloat16 l = __float2bfloat16(v - __bfloat162float(h));
        const size_t o = (size_t)(c0 + ty + 8 * j) * R + r0 + tx;
        dh[o] = h;
        dl[o] = l;
    }
}

// ---------------------------------------------------------------------------
// BatchNorm (training stats) + ReLU on g_h1, in place
// ---------------------------------------------------------------------------
__global__ void zero_stats()
{
    const int i = blockIdx.x * blockDim.x + threadIdx.x;
    if (i < H3) { g_sum[i] = 0.0; g_sq[i] = 0.0; }
}

__global__ void bn_stats(const float* __restrict__ h)
{
    const int col = blockIdx.x * 256 + threadIdx.x;
    const int r0 = blockIdx.y * 256;
    double ls = 0.0, lq = 0.0;
    #pragma unroll 4
    for (int r = r0; r < r0 + 256; r++) {
        const float v = h[(size_t)r * H3 + col];
        ls += (double)v;
        lq += (double)v * (double)v;
    }
    atomicAdd(&g_sum[col], ls);
    atomicAdd(&g_sq[col], lq);
}

__global__ void bn_apply(float* __restrict__ h,
                         const float* __restrict__ gamma,
                         const float* __restrict__ beta)
{
    const size_t i = (size_t)blockIdx.x * blockDim.x + threadIdx.x;
    if (i >= (size_t)NNODE * H3) return;
    const int col = (int)(i % H3);
    const double mu = g_sum[col] / (double)NNODE;
    const double var = g_sq[col] / (double)NNODE - mu * mu;
    const float rstd = rsqrtf((float)var + BN_EPS);
    const float v = (h[i] - (float)mu) * rstd * gamma[col] + beta[col];
    h[i] = v > 0.0f ? v : 0.0f;
}

// ---------------------------------------------------------------------------
// Orchestration
// ---------------------------------------------------------------------------
extern "C" void kernel_launch(void* const* d_in, const int* in_sizes, int n_in,
                              void* d_out, int out_size)
{
    const float* x     = (const float*)d_in[0];
    const float* adj   = (const float*)d_in[1];
    const float* W1    = (const float*)d_in[2];
    const float* b1    = (const float*)d_in[3];
    const float* W2    = (const float*)d_in[4];
    const float* b2    = (const float*)d_in[5];
    const float* gamma = (const float*)d_in[6];
    const float* beta  = (const float*)d_in[7];
    const float* Wf    = (const float*)d_in[8];
    const float* bf    = (const float*)d_in[9];
    float* out = (float*)d_out;

    __nv_bfloat16 *adj_h, *adj_l, *x_h, *x_l, *W1t_h, *W1t_l, *W2t_h, *W2t_l;
    __nv_bfloat16 *Wft_h, *Wft_l, *T1t_h, *T1t_l, *T2t_h, *T2t_l, *T3t_h, *T3t_l;
    __nv_bfloat16 *U12t_h, *U12t_l, *U3t_h, *U3t_l, *h1_h, *h1_l, *h2_h, *h2_l;
    float *h1, *h2;
    cudaGetSymbolAddress((void**)&adj_h, g_adj_h);
    cudaGetSymbolAddress((void**)&adj_l, g_adj_l);
    cudaGetSymbolAddress((void**)&x_h, g_x_h);
    cudaGetSymbolAddress((void**)&x_l, g_x_l);
    cudaGetSymbolAddress((void**)&W1t_h, g_W1t_h);
    cudaGetSymbolAddress((void**)&W1t_l, g_W1t_l);
    cudaGetSymbolAddress((void**)&W2t_h, g_W2t_h);
    cudaGetSymbolAddress((void**)&W2t_l, g_W2t_l);
    cudaGetSymbolAddress((void**)&Wft_h, g_Wft_h);
    cudaGetSymbolAddress((void**)&Wft_l, g_Wft_l);
    cudaGetSymbolAddress((void**)&T1t_h, g_T1t_h);
    cudaGetSymbolAddress((void**)&T1t_l, g_T1t_l);
    cudaGetSymbolAddress((void**)&T2t_h, g_T2t_h);
    cudaGetSymbolAddress((void**)&T2t_l, g_T2t_l);
    cudaGetSymbolAddress((void**)&T3t_h, g_T3t_h);
    cudaGetSymbolAddress((void**)&T3t_l, g_T3t_l);
    cudaGetSymbolAddress((void**)&U12t_h, g_U12t_h);
    cudaGetSymbolAddress((void**)&U12t_l, g_U12t_l);
    cudaGetSymbolAddress((void**)&U3t_h, g_U3t_h);
    cudaGetSymbolAddress((void**)&U3t_l, g_U3t_l);
    cudaGetSymbolAddress((void**)&h1_h, g_h1_h);
    cudaGetSymbolAddress((void**)&h1_l, g_h1_l);
    cudaGetSymbolAddress((void**)&h2_h, g_h2_h);
    cudaGetSymbolAddress((void**)&h2_l, g_h2_l);
    cudaGetSymbolAddress((void**)&h1, g_h1);
    cudaGetSymbolAddress((void**)&h2, g_h2);

    constexpr int SMEM = 2 * 4 * 128 * 32 * 2;   // 65536
    cudaFuncSetAttribute(gemm_mma, cudaFuncAttributeMaxDynamicSharedMemorySize, SMEM);

    const int NOSPLIT = 1 << 30;
    const dim3 blk(256);
    const dim3 g512(4, NNODE / 128);   // N=512
    const dim3 g256(2, NNODE / 128);   // N=256

    // ---- input conversions ----
    cvt_split<<<(unsigned)((size_t)NNODE * IN_DIM / 1024), 256>>>(x, x_h, x_l, (size_t)NNODE * IN_DIM);
    cvt_split<<<(unsigned)((size_t)NNODE * NNODE / 1024), 256>>>(adj, adj_h, adj_l, (size_t)NNODE * NNODE);
    for (int j = 0; j < 3; j++) {
        cvt_split_tr<<<dim3(HID / 32, IN_DIM / 32), dim3(32, 8)>>>(
            W1 + (size_t)j * IN_DIM * HID, W1t_h + (size_t)j * HID * IN_DIM,
            W1t_l + (size_t)j * HID * IN_DIM, IN_DIM, HID);
        cvt_split_tr<<<dim3(OUTD / 32, H3 / 32), dim3(32, 8)>>>(
            W2 + (size_t)j * H3 * OUTD, W2t_h + (size_t)j * OUTD * H3,
            W2t_l + (size_t)j * OUTD * H3, H3, OUTD);
    }
    cvt_split_tr<<<dim3(OUTD / 32, O3 / 32), dim3(32, 8)>>>(Wf, Wft_h, Wft_l, O3, OUTD);

    // ---- Layer 1 linear ----
    gemm_mma<<<g512, blk, SMEM>>>(x_h, x_l, W1t_h, W1t_l, IN_DIM,
        h1, H3, nullptr, nullptr, NOSPLIT, b1);
    gemm_mma<<<g512, blk, SMEM>>>(x_h, x_l,
        W1t_h + HID * IN_DIM, W1t_l + HID * IN_DIM, IN_DIM,
        nullptr, 0, T1t_h, T1t_l, 0, b1 + HID);
    gemm_mma<<<g512, blk, SMEM>>>(x_h, x_l,
        W1t_h + 2 * HID * IN_DIM, W1t_l + 2 * HID * IN_DIM, IN_DIM,
        nullptr, 0, T2t_h, T2t_l, 0, b1 + 2 * HID);

    // ---- Layer 1 propagation ----
    gemm_mma<<<g512, blk, SMEM>>>(adj_h, adj_l, T1t_h, T1t_l, NNODE,
        h1 + HID, H3, nullptr, nullptr, NOSPLIT, nullptr);
    gemm_mma<<<g512, blk, SMEM>>>(adj_h, adj_l, T2t_h, T2t_l, NNODE,
        nullptr, 0, T3t_h, T3t_l, 0, nullptr);
    gemm_mma<<<g512, blk, SMEM>>>(adj_h, adj_l, T3t_h, T3t_l, NNODE,
        h1 + 2 * HID, H3, nullptr, nullptr, NOSPLIT, nullptr);

    // ---- BN + ReLU, then split h1 ----
    zero_stats<<<(H3 + 255) / 256, 256>>>();
    bn_stats<<<dim3(H3 / 256, NNODE / 256), 256>>>(h1);
    {
        const size_t tot = (size_t)NNODE * H3;
        bn_apply<<<(unsigned)((tot + 255) / 256), 256>>>(h1, gamma, beta);
        cvt_split<<<(unsigned)(tot / 1024), 256>>>(h1, h1_h, h1_l, tot);
    }

    // ---- Layer 2 linear ----
    gemm_mma<<<g256, blk, SMEM>>>(h1_h, h1_l, W2t_h, W2t_l, H3,
        h2, O3, nullptr, nullptr, NOSPLIT, b2);
    gemm_mma<<<g256, blk, SMEM>>>(h1_h, h1_l,
        W2t_h + (size_t)OUTD * H3, W2t_l + (size_t)OUTD * H3, H3,
        nullptr, 0, U12t_h, U12t_l, 0, b2 + OUTD);
    gemm_mma<<<g256, blk, SMEM>>>(h1_h, h1_l,
        W2t_h + (size_t)2 * OUTD * H3, W2t_l + (size_t)2 * OUTD * H3, H3,
        nullptr, 0, U12t_h + (size_t)OUTD * NNODE, U12t_l + (size_t)OUTD * NNODE, 0,
        b2 + 2 * OUTD);

    // ---- Layer 2 propagation: fused adj@[U1|U2] (cols<256 -> h2 hop1 fp32,
    //      cols>=256 -> U3^T bf16), then adj@U3 -> h2 hop2 ----
    gemm_mma<<<g512, blk, SMEM>>>(adj_h, adj_l, U12t_h, U12t_l, NNODE,
        h2 + OUTD, O3, U3t_h, U3t_l, OUTD, nullptr);
    gemm_mma<<<g256, blk, SMEM>>>(adj_h, adj_l, U3t_h, U3t_l, NNODE,
        h2 + 2 * OUTD, O3, nullptr, nullptr, NOSPLIT, nullptr);

    // ---- Final projection ----
    {
        const size_t tot = (size_t)NNODE * O3;
        cvt_split<<<(unsigned)(tot / 1024), 256>>>(h2, h2_h, h2_l, tot);
    }
    gemm_mma<<<g256, blk, SMEM>>>(h2_h, h2_l, Wft_h, Wft_l, O3,
        out, OUTD, nullptr, nullptr, NOSPLIT, bf);
}

// round 4
// speedup vs baseline: 2.6721x; 1.1110x over previous
#include <cuda_runtime.h>
#include <cuda_bf16.h>
#include <cstdint>
#include <cstddef>

#define NNODE 8192
#define IN_DIM 128
#define HID 512
#define OUTD 256
#define H3 1536
#define O3 768
#define BN_EPS 1e-5f

// ---------------------------------------------------------------------------
// Device scratch (allocation-free)
// ---------------------------------------------------------------------------
__device__ __nv_bfloat16 g_adj_h[(size_t)NNODE * NNODE];
__device__ __nv_bfloat16 g_adj_l[(size_t)NNODE * NNODE];
__device__ __nv_bfloat16 g_x_h[(size_t)NNODE * IN_DIM];
__device__ __nv_bfloat16 g_x_l[(size_t)NNODE * IN_DIM];
__device__ __nv_bfloat16 g_W1t_h[3 * HID * IN_DIM];      // [1536,128]
__device__ __nv_bfloat16 g_W1t_l[3 * HID * IN_DIM];
__device__ __nv_bfloat16 g_W2t_h[3 * OUTD * H3];         // [768,1536]
__device__ __nv_bfloat16 g_W2t_l[3 * OUTD * H3];
__device__ __nv_bfloat16 g_Wft_h[OUTD * O3];             // [256,768]
__device__ __nv_bfloat16 g_Wft_l[OUTD * O3];
__device__ __nv_bfloat16 g_T12t_h[(size_t)2 * HID * NNODE];  // [1024,8192] = [T1^T ; T2^T]
__device__ __nv_bfloat16 g_T12t_l[(size_t)2 * HID * NNODE];
__device__ __nv_bfloat16 g_T3t_h[(size_t)HID * NNODE];       // [512,8192]
__device__ __nv_bfloat16 g_T3t_l[(size_t)HID * NNODE];
__device__ __nv_bfloat16 g_U12t_h[(size_t)HID * NNODE];      // [512,8192] = [U1^T ; U2^T]
__device__ __nv_bfloat16 g_U12t_l[(size_t)HID * NNODE];
__device__ __nv_bfloat16 g_U3t_h[(size_t)OUTD * NNODE];      // [256,8192]
__device__ __nv_bfloat16 g_U3t_l[(size_t)OUTD * NNODE];
__device__ float g_h1[(size_t)NNODE * H3];
__device__ __nv_bfloat16 g_h1_h[(size_t)NNODE * H3];
__device__ __nv_bfloat16 g_h1_l[(size_t)NNODE * H3];
__device__ __nv_bfloat16 g_h2_h[(size_t)NNODE * O3];
__device__ __nv_bfloat16 g_h2_l[(size_t)NNODE * O3];
__device__ double g_sum[H3];
__device__ double g_sq[H3];

// ---------------------------------------------------------------------------
// PTX helpers (Ampere-era: compile at compute_100)
// ---------------------------------------------------------------------------
__device__ __forceinline__ uint32_t smem_u32(const void* p) {
    uint32_t a;
    asm("{ .reg .u64 t; cvta.to.shared.u64 t, %1; cvt.u32.u64 %0, t; }"
        : "=r"(a) : "l"(p));
    return a;
}

__device__ __forceinline__ void cpa16(uint32_t dst, const void* src) {
    asm volatile("cp.async.cg.shared.global [%0], [%1], 16;" :: "r"(dst), "l"(src));
}
#define CP_COMMIT() asm volatile("cp.async.commit_group;" ::: "memory")
#define CP_WAIT(n)  asm volatile("cp.async.wait_group %0;" :: "n"(n) : "memory")

__device__ __forceinline__ void ldm_x4(uint32_t* r, uint32_t a) {
    asm volatile("ldmatrix.sync.aligned.m8n8.x4.shared.b16 {%0,%1,%2,%3}, [%4];"
        : "=r"(r[0]), "=r"(r[1]), "=r"(r[2]), "=r"(r[3]) : "r"(a));
}

__device__ __forceinline__ void mma_bf16(float* c, const uint32_t* a, const uint32_t* b) {
    asm volatile(
        "mma.sync.aligned.m16n8k16.row.col.f32.bf16.bf16.f32 "
        "{%0,%1,%2,%3}, {%4,%5,%6,%7}, {%8,%9}, {%0,%1,%2,%3};"
        : "+f"(c[0]), "+f"(c[1]), "+f"(c[2]), "+f"(c[3])
        : "r"(a[0]), "r"(a[1]), "r"(a[2]), "r"(a[3]), "r"(b[0]), "r"(b[1]));
}

// smem tile: rows x 32 bf16 (64B/row); XOR swizzle -> conflict-free ldmatrix
__device__ __forceinline__ uint32_t sw_off(int r, int c) {
    return (uint32_t)(r * 64 + ((c ^ ((r >> 1) & 3)) << 4));
}

// ---------------------------------------------------------------------------
// Split-precision bf16 GEMM via mma.sync:
//   C[M,N] = A[M,K] @ B^T   (B stored [N,K] row-major)
//   D += Ah*Bh + Ah*Bl + Al*Bh  (fp32 accum)
// CTA tile 128xBN x32, 256 threads (8 warps, 2x4), warp tile 64x(BN/4).
// 3-stage cp.async pipeline.
// Epilogue (global col gc):
//   gc < splitcol:  Cf != null -> fp32 row-major C (+bias)
//                   else       -> row-major bf16 hi/lo pair (Ch, Cl)
//   gc >= splitcol: transposed bf16 hi/lo  T[(gc-splitcol)*NNODE + row]
// ---------------------------------------------------------------------------
template <int BN>
__global__ void __launch_bounds__(256, 1)
gemm_mma(const __nv_bfloat16* __restrict__ Ah, const __nv_bfloat16* __restrict__ Al,
         const __nv_bfloat16* __restrict__ Bh, const __nv_bfloat16* __restrict__ Bl,
         int K,
         float* __restrict__ Cf,
         __nv_bfloat16* __restrict__ Ch, __nv_bfloat16* __restrict__ Cl, int ldc,
         __nv_bfloat16* __restrict__ Th, __nv_bfloat16* __restrict__ Tl,
         int splitcol, const float* __restrict__ bias)
{
    constexpr int WN = BN / 4;           // warp tile cols (64 or 32)
    constexpr int NT = WN / 8;           // 8-col sub-tiles per warp (8 or 4)
    constexpr int NP = WN / 16;          // ldmatrix.x4 B pairs (4 or 2)
    constexpr int AS = 128 * 32 * 2;     // bytes per A half-tile (8KB)
    constexpr int BS = BN * 32 * 2;      // bytes per B half-tile
    constexpr int OBH = 2 * AS;
    constexpr int OBL = 2 * AS + BS;
    constexpr int STG = 2 * AS + 2 * BS; // stage bytes
    extern __shared__ char smem[];
    const uint32_t sb = smem_u32(smem);

    const int tid = threadIdx.x;
    const int bx = blockIdx.x, by = blockIdx.y;

    // ---- loader mapping: 256 threads -> (row, 2 chunks of 16B) ----
    const int lr = tid >> 1;
    const int lc = (tid & 1) * 2;
    const __nv_bfloat16* pAh = Ah + (size_t)(by * 128 + lr) * K + lc * 8;
    const __nv_bfloat16* pAl = Al + (size_t)(by * 128 + lr) * K + lc * 8;
    const __nv_bfloat16* pBh = Bh + (size_t)(bx * BN + lr) * K + lc * 8;
    const __nv_bfloat16* pBl = Bl + (size_t)(bx * BN + lr) * K + lc * 8;
    const __nv_bfloat16* pBh2 = pBh + (size_t)128 * K;   // BN==256 second block
    const __nv_bfloat16* pBl2 = pBl + (size_t)128 * K;
    const uint32_t d0a = sw_off(lr, lc);
    const uint32_t d1a = sw_off(lr, lc + 1);

    // ---- compute mapping: 8 warps, 2 rows x 4 cols ----
    const int w = tid >> 5, l = tid & 31;
    const int RM = (w >> 2) * 64;
    const int CN = (w & 3) * WN;

    uint32_t aoff[4][2];
    #pragma unroll
    for (int mt = 0; mt < 4; mt++) {
        const int r = RM + mt * 16 + (l & 15);
        #pragma unroll
        for (int ks = 0; ks < 2; ks++)
            aoff[mt][ks] = sw_off(r, ks * 2 + (l >> 4));
    }
    uint32_t boff[NP][2];
    #pragma unroll
    for (int np = 0; np < NP; np++) {
        const int r = CN + np * 16 + ((l >> 4) << 3) + (l & 7);
        #pragma unroll
        for (int ks = 0; ks < 2; ks++)
            boff[np][ks] = sw_off(r, ks * 2 + ((l >> 3) & 1));
    }

    float acc[4][NT][4];
    #pragma unroll
    for (int mt = 0; mt < 4; mt++)
        #pragma unroll
        for (int nt = 0; nt < NT; nt++)
            #pragma unroll
            for (int k = 0; k < 4; k++) acc[mt][nt][k] = 0.0f;

    const int nk = K >> 5;

    auto load_stage = [&](int c) {
        const int k0 = c << 5;
        const uint32_t ds = (uint32_t)(c % 3) * STG;
        cpa16(sb + ds + d0a, pAh + k0);
        cpa16(sb + ds + d1a, pAh + k0 + 8);
        cpa16(sb + ds + AS + d0a, pAl + k0);
        cpa16(sb + ds + AS + d1a, pAl + k0 + 8);
        cpa16(sb + ds + OBH + d0a, pBh + k0);
        cpa16(sb + ds + OBH + d1a, pBh + k0 + 8);
        cpa16(sb + ds + OBL + d0a, pBl + k0);
        cpa16(sb + ds + OBL + d1a, pBl + k0 + 8);
        if (BN == 256) {
            cpa16(sb + ds + OBH + 8192 + d0a, pBh2 + k0);
            cpa16(sb + ds + OBH + 8192 + d1a, pBh2 + k0 + 8);
            cpa16(sb + ds + OBL + 8192 + d0a, pBl2 + k0);
            cpa16(sb + ds + OBL + 8192 + d1a, pBl2 + k0 + 8);
        }
    };

    load_stage(0); CP_COMMIT();
    if (nk > 1) { load_stage(1); CP_COMMIT(); }

    for (int c = 0; c < nk; c++) {
        if (c + 1 < nk) { CP_WAIT(1); } else { CP_WAIT(0); }
        __syncthreads();
        if (c + 2 < nk) { load_stage(c + 2); CP_COMMIT(); }

        const uint32_t sbase = sb + (uint32_t)(c % 3) * STG;
        #pragma unroll
        for (int ks = 0; ks < 2; ks++) {
            uint32_t ahf[4][4], alf[4][4];
            #pragma unroll
            for (int mt = 0; mt < 4; mt++) {
                ldm_x4(ahf[mt], sbase + aoff[mt][ks]);
                ldm_x4(alf[mt], sbase + AS + aoff[mt][ks]);
            }
            #pragma unroll
            for (int np = 0; np < NP; np++) {
                uint32_t bh[4], bl[4];
                ldm_x4(bh, sbase + OBH + boff[np][ks]);
                ldm_x4(bl, sbase + OBL + boff[np][ks]);
                #pragma unroll
                for (int mt = 0; mt < 4; mt++)
                    #pragma unroll
                    for (int s = 0; s < 2; s++) {
                        float* a = acc[mt][2 * np + s];
                        mma_bf16(a, ahf[mt], &bh[s * 2]);
                        mma_bf16(a, ahf[mt], &bl[s * 2]);
                        mma_bf16(a, alf[mt], &bh[s * 2]);
                    }
            }
        }
    }

    // ---- epilogue ----
    #pragma unroll
    for (int mt = 0; mt < 4; mt++) {
        const int r0 = by * 128 + RM + mt * 16 + (l >> 2);
        #pragma unroll
        for (int nt = 0; nt < NT; nt++) {
            const int gc = bx * BN + CN + nt * 8 + ((l & 3) << 1);
            float v0 = acc[mt][nt][0], v1 = acc[mt][nt][1];
            float v2 = acc[mt][nt][2], v3 = acc[mt][nt][3];
            if (bias) {
                const float bb0 = __ldg(bias + gc), bb1 = __ldg(bias + gc + 1);
                v0 += bb0; v1 += bb1; v2 += bb0; v3 += bb1;
            }
            if (gc < splitcol) {
                if (Cf) {
                    *(float2*)&Cf[(size_t)r0 * ldc + gc] = make_float2(v0, v1);
                    *(float2*)&Cf[(size_t)(r0 + 8) * ldc + gc] = make_float2(v2, v3);
                } else {
                    const __nv_bfloat16 h0 = __float2bfloat16(v0);
                    const __nv_bfloat16 h1 = __float2bfloat16(v1);
                    const __nv_bfloat16 h2 = __float2bfloat16(v2);
                    const __nv_bfloat16 h3 = __float2bfloat16(v3);
                    *(__nv_bfloat162*)&Ch[(size_t)r0 * ldc + gc] = __halves2bfloat162(h0, h1);
                    *(__nv_bfloat162*)&Ch[(size_t)(r0 + 8) * ldc + gc] = __halves2bfloat162(h2, h3);
                    *(__nv_bfloat162*)&Cl[(size_t)r0 * ldc + gc] = __halves2bfloat162(
                        __float2bfloat16(v0 - __bfloat162float(h0)),
                        __float2bfloat16(v1 - __bfloat162float(h1)));
                    *(__nv_bfloat162*)&Cl[(size_t)(r0 + 8) * ldc + gc] = __halves2bfloat162(
                        __float2bfloat16(v2 - __bfloat162float(h2)),
                        __float2bfloat16(v3 - __bfloat162float(h3)));
                }
            } else {
                const size_t o0 = (size_t)(gc - splitcol) * NNODE;
                const size_t o1 = o0 + NNODE;
                float vv[4] = {v0, v1, v2, v3};
                size_t oo[4] = {o0 + r0, o1 + r0, o0 + r0 + 8, o1 + r0 + 8};
                #pragma unroll
                for (int q = 0; q < 4; q++) {
                    const __nv_bfloat16 h = __float2bfloat16(vv[q]);
                    Th[oo[q]] = h;
                    Tl[oo[q]] = __float2bfloat16(vv[q] - __bfloat162float(h));
                }
            }
        }
    }
}

// ---------------------------------------------------------------------------
// fp32 -> (bf16 hi, bf16 lo) converters
// ---------------------------------------------------------------------------
__global__ void cvt_split(const float* __restrict__ s,
                          __nv_bfloat16* __restrict__ h,
                          __nv_bfloat16* __restrict__ l, size_t n)
{
    const size_t i = ((size_t)blockIdx.x * 256 + threadIdx.x) * 4;
    if (i >= n) return;
    const float4 v = *(const float4*)(s + i);
    float a[4] = {v.x, v.y, v.z, v.w};
    __nv_bfloat16 hh[4], ll[4];
    #pragma unroll
    for (int k = 0; k < 4; k++) {
        hh[k] = __float2bfloat16(a[k]);
        ll[k] = __float2bfloat16(a[k] - __bfloat162float(hh[k]));
    }
    ((__nv_bfloat162*)(h + i))[0] = __halves2bfloat162(hh[0], hh[1]);
    ((__nv_bfloat162*)(h + i))[1] = __halves2bfloat162(hh[2], hh[3]);
    ((__nv_bfloat162*)(l + i))[0] = __halves2bfloat162(ll[0], ll[1]);
    ((__nv_bfloat162*)(l + i))[1] = __halves2bfloat162(ll[2], ll[3]);
}

// [R,C] fp32 -> [C,R] bf16 hi/lo
__global__ void cvt_split_tr(const float* __restrict__ s,
                             __nv_bfloat16* __restrict__ dh,
                             __nv_bfloat16* __restrict__ dl, int R, int C)
{
    __shared__ float t[32][33];
    const int c0 = blockIdx.x * 32, r0 = blockIdx.y * 32;
    const int tx = threadIdx.x, ty = threadIdx.y;
    #pragma unroll
    for (int j = 0; j < 4; j++)
        t[ty + 8 * j][tx] = s[(size_t)(r0 + ty + 8 * j) * C + c0 + tx];
    __syncthreads();
    #pragma unroll
    for (int j = 0; j < 4; j++) {
        const float v = t[tx][ty + 8 * j];
        const __nv_bfloat16 h = __float2bfloat16(v);
        const __nv_bfloat16 l = __float2bfloat16(v - __bfloat162float(h));
        const size_t o = (size_t)(c0 + ty + 8 * j) * R + r0 + tx;
        dh[o] = h;
        dl[o] = l;
    }
}

// ---------------------------------------------------------------------------
// BatchNorm (training stats) + ReLU; writes split bf16 pair directly
// ---------------------------------------------------------------------------
__global__ void zero_stats()
{
    const int i = blockIdx.x * blockDim.x + threadIdx.x;
    if (i < H3) { g_sum[i] = 0.0; g_sq[i] = 0.0; }
}

__global__ void bn_stats(const float* __restrict__ h)
{
    const int col = blockIdx.x * 256 + threadIdx.x;
    const int r0 = blockIdx.y * 256;
    double ls = 0.0, lq = 0.0;
    #pragma unroll 4
    for (int r = r0; r < r0 + 256; r++) {
        const float v = h[(size_t)r * H3 + col];
        ls += (double)v;
        lq += (double)v * (double)v;
    }
    atomicAdd(&g_sum[col], ls);
    atomicAdd(&g_sq[col], lq);
}

__global__ void bn_apply(const float* __restrict__ h,
                         const float* __restrict__ gamma,
                         const float* __restrict__ beta,
                         __nv_bfloat16* __restrict__ oh,
                         __nv_bfloat16* __restrict__ ol)
{
    const size_t i = (size_t)blockIdx.x * blockDim.x + threadIdx.x;
    if (i >= (size_t)NNODE * H3) return;
    const int col = (int)(i % H3);
    const double mu = g_sum[col] / (double)NNODE;
    const double var = g_sq[col] / (double)NNODE - mu * mu;
    const float rstd = rsqrtf((float)var + BN_EPS);
    float v = (h[i] - (float)mu) * rstd * gamma[col] + beta[col];
    v = v > 0.0f ? v : 0.0f;
    const __nv_bfloat16 hi = __float2bfloat16(v);
    oh[i] = hi;
    ol[i] = __float2bfloat16(v - __bfloat162float(hi));
}

// ---------------------------------------------------------------------------
// Orchestration
// ---------------------------------------------------------------------------
extern "C" void kernel_launch(void* const* d_in, const int* in_sizes, int n_in,
                              void* d_out, int out_size)
{
    const float* x     = (const float*)d_in[0];
    const float* adj   = (const float*)d_in[1];
    const float* W1    = (const float*)d_in[2];
    const float* b1    = (const float*)d_in[3];
    const float* W2    = (const float*)d_in[4];
    const float* b2    = (const float*)d_in[5];
    const float* gamma = (const float*)d_in[6];
    const float* beta  = (const float*)d_in[7];
    const float* Wf    = (const float*)d_in[8];
    const float* bf    = (const float*)d_in[9];
    float* out = (float*)d_out;

    __nv_bfloat16 *adj_h, *adj_l, *x_h, *x_l, *W1t_h, *W1t_l, *W2t_h, *W2t_l;
    __nv_bfloat16 *Wft_h, *Wft_l, *T12t_h, *T12t_l, *T3t_h, *T3t_l;
    __nv_bfloat16 *U12t_h, *U12t_l, *U3t_h, *U3t_l, *h1_h, *h1_l, *h2_h, *h2_l;
    float *h1;
    cudaGetSymbolAddress((void**)&adj_h, g_adj_h);
    cudaGetSymbolAddress((void**)&adj_l, g_adj_l);
    cudaGetSymbolAddress((void**)&x_h, g_x_h);
    cudaGetSymbolAddress((void**)&x_l, g_x_l);
    cudaGetSymbolAddress((void**)&W1t_h, g_W1t_h);
    cudaGetSymbolAddress((void**)&W1t_l, g_W1t_l);
    cudaGetSymbolAddress((void**)&W2t_h, g_W2t_h);
    cudaGetSymbolAddress((void**)&W2t_l, g_W2t_l);
    cudaGetSymbolAddress((void**)&Wft_h, g_Wft_h);
    cudaGetSymbolAddress((void**)&Wft_l, g_Wft_l);
    cudaGetSymbolAddress((void**)&T12t_h, g_T12t_h);
    cudaGetSymbolAddress((void**)&T12t_l, g_T12t_l);
    cudaGetSymbolAddress((void**)&T3t_h, g_T3t_h);
    cudaGetSymbolAddress((void**)&T3t_l, g_T3t_l);
    cudaGetSymbolAddress((void**)&U12t_h, g_U12t_h);
    cudaGetSymbolAddress((void**)&U12t_l, g_U12t_l);
    cudaGetSymbolAddress((void**)&U3t_h, g_U3t_h);
    cudaGetSymbolAddress((void**)&U3t_l, g_U3t_l);
    cudaGetSymbolAddress((void**)&h1_h, g_h1_h);
    cudaGetSymbolAddress((void**)&h1_l, g_h1_l);
    cudaGetSymbolAddress((void**)&h2_h, g_h2_h);
    cudaGetSymbolAddress((void**)&h2_l, g_h2_l);
    cudaGetSymbolAddress((void**)&h1, g_h1);

    constexpr int STG256 = 2 * (128 * 32 * 2) + 2 * (256 * 32 * 2);  // 49152
    constexpr int STG128 = 2 * (128 * 32 * 2) + 2 * (128 * 32 * 2);  // 32768
    constexpr int SMEM256 = 3 * STG256;   // 147456
    constexpr int SMEM128 = 3 * STG128;   // 98304
    cudaFuncSetAttribute(gemm_mma<256>, cudaFuncAttributeMaxDynamicSharedMemorySize, SMEM256);
    cudaFuncSetAttribute(gemm_mma<128>, cudaFuncAttributeMaxDynamicSharedMemorySize, SMEM128);

    const int NOSPLIT = 1 << 30;
    const dim3 blk(256);
    const int MB = NNODE / 128;   // 64

    // ---- input conversions ----
    cvt_split<<<(unsigned)((size_t)NNODE * IN_DIM / 1024), 256>>>(x, x_h, x_l, (size_t)NNODE * IN_DIM);
    cvt_split<<<(unsigned)((size_t)NNODE * NNODE / 1024), 256>>>(adj, adj_h, adj_l, (size_t)NNODE * NNODE);
    for (int j = 0; j < 3; j++) {
        cvt_split_tr<<<dim3(HID / 32, IN_DIM / 32), dim3(32, 8)>>>(
            W1 + (size_t)j * IN_DIM * HID, W1t_h + (size_t)j * HID * IN_DIM,
            W1t_l + (size_t)j * HID * IN_DIM, IN_DIM, HID);
        cvt_split_tr<<<dim3(OUTD / 32, H3 / 32), dim3(32, 8)>>>(
            W2 + (size_t)j * H3 * OUTD, W2t_h + (size_t)j * OUTD * H3,
            W2t_l + (size_t)j * OUTD * H3, H3, OUTD);
    }
    cvt_split_tr<<<dim3(OUTD / 32, O3 / 32), dim3(32, 8)>>>(Wf, Wft_h, Wft_l, O3, OUTD);

    // ---- GEMM 1: x @ [W1_0|W1_1|W1_2]  (N=1536; cols<512 -> h1 fp32, >=512 -> T12^T) ----
    gemm_mma<256><<<dim3(6, MB), blk, SMEM256>>>(x_h, x_l, W1t_h, W1t_l, IN_DIM,
        h1, nullptr, nullptr, H3, T12t_h, T12t_l, 512, b1);

    // ---- GEMM 2: adj @ [T1|T2]  (N=1024; cols<512 -> h1 hop1 fp32, >=512 -> T3^T) ----
    gemm_mma<256><<<dim3(4, MB), blk, SMEM256>>>(adj_h, adj_l, T12t_h, T12t_l, NNODE,
        h1 + HID, nullptr, nullptr, H3, T3t_h, T3t_l, 512, nullptr);

    // ---- GEMM 3: adj @ T3  (N=512 -> h1 hop2 fp32) ----
    gemm_mma<256><<<dim3(2, MB), blk, SMEM256>>>(adj_h, adj_l, T3t_h, T3t_l, NNODE,
        h1 + 2 * HID, nullptr, nullptr, H3, nullptr, nullptr, NOSPLIT, nullptr);

    // ---- BN + ReLU -> h1 split bf16 ----
    zero_stats<<<(H3 + 255) / 256, 256>>>();
    bn_stats<<<dim3(H3 / 256, NNODE / 256), 256>>>(h1);
    {
        const size_t tot = (size_t)NNODE * H3;
        bn_apply<<<(unsigned)((tot + 255) / 256), 256>>>(h1, gamma, beta, h1_h, h1_l);
    }

    // ---- GEMM 4: h1 @ [W2_0|W2_1|W2_2]  (N=768; cols<256 -> h2 row bf16, >=256 -> U12^T) ----
    gemm_mma<256><<<dim3(3, MB), blk, SMEM256>>>(h1_h, h1_l, W2t_h, W2t_l, H3,
        nullptr, h2_h, h2_l, O3, U12t_h, U12t_l, 256, b2);

    // ---- GEMM 5: adj @ [U1|U2]  (N=512; cols<256 -> h2 hop1 row bf16, >=256 -> U3^T) ----
    gemm_mma<256><<<dim3(2, MB), blk, SMEM256>>>(adj_h, adj_l, U12t_h, U12t_l, NNODE,
        nullptr, h2_h + OUTD, h2_l + OUTD, O3, U3t_h, U3t_l, 256, nullptr);

    // ---- GEMM 6: adj @ U3  (N=256 -> h2 hop2 row bf16) ----
    gemm_mma<128><<<dim3(2, MB), blk, SMEM128>>>(adj_h, adj_l, U3t_h, U3t_l, NNODE,
        nullptr, h2_h + 2 * OUTD, h2_l + 2 * OUTD, O3, nullptr, nullptr, NOSPLIT, nullptr);

    // ---- GEMM 7: out = h2 @ Wf + bf  (N=256, fp32) ----
    gemm_mma<128><<<dim3(2, MB), blk, SMEM128>>>(h2_h, h2_l, Wft_h, Wft_l, O3,
        out, nullptr, nullptr, OUTD, nullptr, nullptr, NOSPLIT, bf);
}

// round 5
// speedup vs baseline: 3.4352x; 1.2856x over previous
#include <cuda_runtime.h>
#include <cuda_bf16.h>
#include <cstdint>
#include <cstddef>

#define NNODE 8192
#define IN_DIM 128
#define HID 512
#define OUTD 256
#define H3 1536
#define O3 768
#define BN_EPS 1e-5f

// ---------------------------------------------------------------------------
// Device scratch (allocation-free). All GEMM operands live in PCS layout:
//   [R,K] bf16 -> 8KB blocks: block(p = r>>7, c = k>>5) at ((p*(K/32)+c)<<13),
//   within-block: sw_off(r&127, (k&31)>>3) + (k&7)*2  (XOR-swizzled 128x32)
// ---------------------------------------------------------------------------
__device__ __align__(1024) __nv_bfloat16 g_adj_h[(size_t)NNODE * NNODE];
__device__ __align__(1024) __nv_bfloat16 g_adj_l[(size_t)NNODE * NNODE];
__device__ __align__(1024) __nv_bfloat16 g_x_h[(size_t)NNODE * IN_DIM];
__device__ __align__(1024) __nv_bfloat16 g_x_l[(size_t)NNODE * IN_DIM];
__device__ __align__(1024) __nv_bfloat16 g_W1t_h[3 * HID * IN_DIM];      // [1536,128]
__device__ __align__(1024) __nv_bfloat16 g_W1t_l[3 * HID * IN_DIM];
__device__ __align__(1024) __nv_bfloat16 g_W2t_h[3 * OUTD * H3];         // [768,1536]
__device__ __align__(1024) __nv_bfloat16 g_W2t_l[3 * OUTD * H3];
__device__ __align__(1024) __nv_bfloat16 g_Wft_h[OUTD * O3];             // [256,768]
__device__ __align__(1024) __nv_bfloat16 g_Wft_l[OUTD * O3];
__device__ __align__(1024) __nv_bfloat16 g_T12t_h[(size_t)2 * HID * NNODE]; // [1024,8192]
__device__ __align__(1024) __nv_bfloat16 g_T12t_l[(size_t)2 * HID * NNODE];
__device__ __align__(1024) __nv_bfloat16 g_T3t_h[(size_t)HID * NNODE];      // [512,8192]
__device__ __align__(1024) __nv_bfloat16 g_T3t_l[(size_t)HID * NNODE];
__device__ __align__(1024) __nv_bfloat16 g_U12t_h[(size_t)HID * NNODE];     // [512,8192]
__device__ __align__(1024) __nv_bfloat16 g_U12t_l[(size_t)HID * NNODE];
__device__ __align__(1024) __nv_bfloat16 g_U3t_h[(size_t)OUTD * NNODE];     // [256,8192]
__device__ __align__(1024) __nv_bfloat16 g_U3t_l[(size_t)OUTD * NNODE];
__device__ float g_h1[(size_t)NNODE * H3];                                  // row-major fp32
__device__ __align__(1024) __nv_bfloat16 g_h1_h[(size_t)NNODE * H3];        // PCS [8192,1536]
__device__ __align__(1024) __nv_bfloat16 g_h1_l[(size_t)NNODE * H3];
__device__ __align__(1024) __nv_bfloat16 g_h2_h[(size_t)NNODE * O3];        // PCS [8192,768]
__device__ __align__(1024) __nv_bfloat16 g_h2_l[(size_t)NNODE * O3];
__device__ double g_sum[H3];
__device__ double g_sq[H3];

// ---------------------------------------------------------------------------
// PTX helpers (all sm_90-baseline: compile at compute_100)
// ---------------------------------------------------------------------------
__device__ __forceinline__ uint32_t smem_u32(const void* p) {
    uint32_t a;
    asm("{ .reg .u64 t; cvta.to.shared.u64 t, %1; cvt.u32.u64 %0, t; }"
        : "=r"(a) : "l"(p));
    return a;
}

__device__ __forceinline__ void ldm_x4(uint32_t* r, uint32_t a) {
    asm volatile("ldmatrix.sync.aligned.m8n8.x4.shared.b16 {%0,%1,%2,%3}, [%4];"
        : "=r"(r[0]), "=r"(r[1]), "=r"(r[2]), "=r"(r[3]) : "r"(a));
}

__device__ __forceinline__ void mma_bf16(float* c, const uint32_t* a, const uint32_t* b) {
    asm volatile(
        "mma.sync.aligned.m16n8k16.row.col.f32.bf16.bf16.f32 "
        "{%0,%1,%2,%3}, {%4,%5,%6,%7}, {%8,%9}, {%0,%1,%2,%3};"
        : "+f"(c[0]), "+f"(c[1]), "+f"(c[2]), "+f"(c[3])
        : "r"(a[0]), "r"(a[1]), "r"(a[2]), "r"(a[3]), "r"(b[0]), "r"(b[1]));
}

// swizzled offset within an 8KB 128x32 bf16 block; c = 16B-chunk index 0..3
__device__ __forceinline__ uint32_t sw_off(int r, int c) {
    return (uint32_t)(r * 64 + ((c ^ ((r >> 1) & 3)) << 4));
}

// byte offset of element (r,k) in a PCS bf16 matrix with K columns
__device__ __forceinline__ size_t pcs_off(int r, int k, int K) {
    const size_t blk = ((size_t)(r >> 7) * (size_t)(K >> 5) + (size_t)(k >> 5)) << 13;
    return blk + sw_off(r & 127, (k & 31) >> 3) + (size_t)((k & 7) * 2);
}

#define MBAR_INIT(a, n) \
    asm volatile("mbarrier.init.shared.b64 [%0], %1;" :: "r"(a), "r"((uint32_t)(n)) : "memory")
#define MBAR_EXPECT(a, n) \
    asm volatile("mbarrier.arrive.expect_tx.shared.b64 _, [%0], %1;" \
                 :: "r"(a), "r"((uint32_t)(n)) : "memory")

#define MBAR_WAIT(a, ph) do {                                                     \
    uint32_t _m = (a); uint32_t _p = (uint32_t)(ph); uint32_t _d;                 \
    asm volatile(                                                                 \
        "{\n\t.reg .pred p;\n\t"                                                  \
        "mbarrier.try_wait.parity.acquire.cta.shared::cta.b64 p, [%1], %2;\n\t"   \
        "selp.b32 %0, 1, 0, p;\n\t}"                                              \
        : "=r"(_d) : "r"(_m), "r"(_p) : "memory");                                \
    if (!_d) {                                                                    \
        asm volatile(                                                             \
            "{\n\t.reg .pred P1;\n\t"                                             \
            "WL_%=:\n\t"                                                          \
            "mbarrier.try_wait.parity.acquire.cta.shared::cta.b64 P1, [%0], %1, 0x989680;\n\t" \
            "@P1 bra.uni WD_%=;\n\t"                                              \
            "bra.uni WL_%=;\n\t"                                                  \
            "WD_%=:\n\t}"                                                         \
            :: "r"(_m), "r"(_p) : "memory");                                      \
    }                                                                             \
} while (0)

// 8KB bulk copy global -> shared with mbarrier transaction tracking
__device__ __forceinline__ void bulk_g2s(uint32_t dst, const void* src, uint32_t mbar) {
    asm volatile(
        "cp.async.bulk.shared::cluster.global.mbarrier::complete_tx::bytes [%0], [%1], %2, [%3];"
        :: "r"(dst), "l"(src), "r"(8192u), "r"(mbar) : "memory");
}

// ---------------------------------------------------------------------------
// Split-precision bf16 GEMM via mma.sync, bulk-copy loader:
//   C[M,N] = A[M,K] @ B^T    (A: PCS [M,K]; B: PCS [N,K])
//   D += Ah*Bh + Ah*Bl + Al*Bh  (fp32 accum)
// CTA tile 128xBNx32, 256 threads (8 warps, 2x4), warp tile 64x(BN/4).
// 4-stage pipeline, 8KB cp.async.bulk per panel-chunk, mbarrier per stage.
// Epilogue (global col gc):
//   gc < splitcol:  Cf != null -> fp32 row-major C (+bias)
//                   else       -> PCS bf16 hi/lo (Ch, Cl), K=ldc, col gc+colofs
//   gc >= splitcol: transposed PCS bf16 hi/lo T at (gc-splitcol, row), K=NNODE
// ---------------------------------------------------------------------------
template <int BN>
__global__ void __launch_bounds__(256, 1)
gemm_mma(const __nv_bfloat16* __restrict__ Ah, const __nv_bfloat16* __restrict__ Al,
         const __nv_bfloat16* __restrict__ Bh, const __nv_bfloat16* __restrict__ Bl,
         int K,
         float* __restrict__ Cf,
         __nv_bfloat16* __restrict__ Ch, __nv_bfloat16* __restrict__ Cl,
         int ldc, int colofs,
         __nv_bfloat16* __restrict__ Th, __nv_bfloat16* __restrict__ Tl,
         int splitcol, const float* __restrict__ bias)
{
    constexpr int WN = BN / 4;            // warp tile cols
    constexpr int NT = WN / 8;
    constexpr int NP = WN / 16;
    constexpr int NPAN = BN / 128;        // B panels per CTA tile
    constexpr int AS = 8192;              // A half-tile bytes
    constexpr int OBH = 2 * AS;
    constexpr int OBL = 2 * AS + NPAN * 8192;
    constexpr int STG = (2 + 2 * NPAN) * 8192;
    extern __shared__ char smem[];
    const uint32_t sb = smem_u32(smem);
    const uint32_t db = sb + 1024;

    const int tid = threadIdx.x;
    const int bx = blockIdx.x, by = blockIdx.y;
    const int KC = K >> 5;

    if (tid == 0) {
        #pragma unroll
        for (int b = 0; b < 4; b++) MBAR_INIT(sb + 8 * b, 1);
    }
    __syncthreads();

    auto issue = [&](int c) {
        const int b = c & 3;
        const uint32_t mb = sb + 8 * b;
        const uint32_t dst = db + (uint32_t)b * STG;
        MBAR_EXPECT(mb, STG);
        bulk_g2s(dst,      (const char*)Ah + (((size_t)by * KC + c) << 13), mb);
        bulk_g2s(dst + AS, (const char*)Al + (((size_t)by * KC + c) << 13), mb);
        #pragma unroll
        for (int p = 0; p < NPAN; p++) {
            const size_t bo = ((size_t)(bx * NPAN + p) * KC + c) << 13;
            bulk_g2s(dst + OBH + p * 8192, (const char*)Bh + bo, mb);
            bulk_g2s(dst + OBL + p * 8192, (const char*)Bl + bo, mb);
        }
    };

    if (tid == 0) {
        issue(0);
        if (KC > 1) issue(1);
        if (KC > 2) issue(2);
    }

    // ---- compute mapping: 8 warps, 2 rows x 4 cols ----
    const int w = tid >> 5, l = tid & 31;
    const int RM = (w >> 2) * 64;
    const int CN = (w & 3) * WN;

    uint32_t aoff[4][2];
    #pragma unroll
    for (int mt = 0; mt < 4; mt++) {
        const int r = RM + mt * 16 + (l & 15);
        #pragma unroll
        for (int ks = 0; ks < 2; ks++)
            aoff[mt][ks] = sw_off(r, ks * 2 + (l >> 4));
    }
    uint32_t boff[NP][2];
    #pragma unroll
    for (int np = 0; np < NP; np++) {
        const int r = CN + np * 16 + ((l >> 4) << 3) + (l & 7);
        #pragma unroll
        for (int ks = 0; ks < 2; ks++)
            boff[np][ks] = sw_off(r, ks * 2 + ((l >> 3) & 1));
    }

    float acc[4][NT][4];
    #pragma unroll
    for (int mt = 0; mt < 4; mt++)
        #pragma unroll
        for (int nt = 0; nt < NT; nt++)
            #pragma unroll
            for (int k = 0; k < 4; k++) acc[mt][nt][k] = 0.0f;

    for (int c = 0; c < KC; c++) {
        MBAR_WAIT(sb + 8 * (c & 3), (c >> 2) & 1);

        const uint32_t sbase = db + (uint32_t)(c & 3) * STG;
        #pragma unroll
        for (int ks = 0; ks < 2; ks++) {
            uint32_t ahf[4][4], alf[4][4];
            #pragma unroll
            for (int mt = 0; mt < 4; mt++) {
                ldm_x4(ahf[mt], sbase + aoff[mt][ks]);
                ldm_x4(alf[mt], sbase + AS + aoff[mt][ks]);
            }
            #pragma unroll
            for (int np = 0; np < NP; np++) {
                uint32_t bh[4], bl[4];
                ldm_x4(bh, sbase + OBH + boff[np][ks]);
                ldm_x4(bl, sbase + OBL + boff[np][ks]);
                #pragma unroll
                for (int mt = 0; mt < 4; mt++)
                    #pragma unroll
                    for (int s = 0; s < 2; s++) {
                        float* a = acc[mt][2 * np + s];
                        mma_bf16(a, ahf[mt], &bh[s * 2]);
                        mma_bf16(a, ahf[mt], &bl[s * 2]);
                        mma_bf16(a, alf[mt], &bh[s * 2]);
                    }
            }
        }
        __syncthreads();
        if (tid == 0 && c + 3 < KC) issue(c + 3);
    }

    // ---- epilogue ----
    #pragma unroll
    for (int mt = 0; mt < 4; mt++) {
        const int r0 = by * 128 + RM + mt * 16 + (l >> 2);
        #pragma unroll
        for (int nt = 0; nt < NT; nt++) {
            const int gc = bx * BN + CN + nt * 8 + ((l & 3) << 1);
            float v0 = acc[mt][nt][0], v1 = acc[mt][nt][1];
            float v2 = acc[mt][nt][2], v3 = acc[mt][nt][3];
            if (bias) {
                const float bb0 = __ldg(bias + gc), bb1 = __ldg(bias + gc + 1);
                v0 += bb0; v1 += bb1; v2 += bb0; v3 += bb1;
            }
            if (gc < splitcol) {
                if (Cf) {
                    *(float2*)&Cf[(size_t)r0 * ldc + gc] = make_float2(v0, v1);
                    *(float2*)&Cf[(size_t)(r0 + 8) * ldc + gc] = make_float2(v2, v3);
                } else {
                    const int pc = gc + colofs;
                    const __nv_bfloat16 h0 = __float2bfloat16(v0);
                    const __nv_bfloat16 h1 = __float2bfloat16(v1);
                    const __nv_bfloat16 h2 = __float2bfloat16(v2);
                    const __nv_bfloat16 h3 = __float2bfloat16(v3);
                    const size_t oA = pcs_off(r0, pc, ldc);
                    const size_t oB = pcs_off(r0 + 8, pc, ldc);
                    *(__nv_bfloat162*)((char*)Ch + oA) = __halves2bfloat162(h0, h1);
                    *(__nv_bfloat162*)((char*)Ch + oB) = __halves2bfloat162(h2, h3);
                    *(__nv_bfloat162*)((char*)Cl + oA) = __halves2bfloat162(
                        __float2bfloat16(v0 - __bfloat162float(h0)),
                        __float2bfloat16(v1 - __bfloat162float(h1)));
                    *(__nv_bfloat162*)((char*)Cl + oB) = __halves2bfloat162(
                        __float2bfloat16(v2 - __bfloat162float(h2)),
                        __float2bfloat16(v3 - __bfloat162float(h3)));
                }
            } else {
                const int tr = gc - splitcol;
                const float vv[4] = {v0, v1, v2, v3};
                const size_t oo[4] = {
                    pcs_off(tr, r0, NNODE), pcs_off(tr + 1, r0, NNODE),
                    pcs_off(tr, r0 + 8, NNODE), pcs_off(tr + 1, r0 + 8, NNODE)};
                #pragma unroll
                for (int q = 0; q < 4; q++) {
                    const __nv_bfloat16 h = __float2bfloat16(vv[q]);
                    *(__nv_bfloat16*)((char*)Th + oo[q]) = h;
                    *(__nv_bfloat16*)((char*)Tl + oo[q]) =
                        __float2bfloat16(vv[q] - __bfloat162float(h));
                }
            }
        }
    }
}

// ---------------------------------------------------------------------------
// fp32 row-major [R,K] -> PCS bf16 hi/lo
// ---------------------------------------------------------------------------
__global__ void cvt_split_pcs(const float* __restrict__ s,
                              __nv_bfloat16* __restrict__ dh,
                              __nv_bfloat16* __restrict__ dl, int R, int K)
{
    const int K8 = K >> 3;
    const size_t i8 = (size_t)blockIdx.x * 256 + threadIdx.x;
    if (i8 >= (size_t)R * K8) return;
    const int r = (int)(i8 / K8);
    const int k = (int)(i8 % K8) << 3;
    const float4 u0 = *(const float4*)(s + (size_t)r * K + k);
    const float4 u1 = *(const float4*)(s + (size_t)r * K + k + 4);
    const float a[8] = {u0.x, u0.y, u0.z, u0.w, u1.x, u1.y, u1.z, u1.w};
    __nv_bfloat16 hh[8], ll[8];
    #pragma unroll
    for (int q = 0; q < 8; q++) {
        hh[q] = __float2bfloat16(a[q]);
        ll[q] = __float2bfloat16(a[q] - __bfloat162float(hh[q]));
    }
    const size_t o = pcs_off(r, k, K);
    __nv_bfloat162* ph = (__nv_bfloat162*)((char*)dh + o);
    __nv_bfloat162* pl = (__nv_bfloat162*)((char*)dl + o);
    #pragma unroll
    for (int q = 0; q < 4; q++) {
        ph[q] = __halves2bfloat162(hh[2 * q], hh[2 * q + 1]);
        pl[q] = __halves2bfloat162(ll[2 * q], ll[2 * q + 1]);
    }
}

// fp32 [R,C] row-major -> transposed PCS bf16 hi/lo [C rows, R cols]
__global__ void cvt_split_tr_pcs(const float* __restrict__ s,
                                 __nv_bfloat16* __restrict__ dh,
                                 __nv_bfloat16* __restrict__ dl, int R, int C)
{
    __shared__ float t[32][33];
    const int c0 = blockIdx.x * 32, r0 = blockIdx.y * 32;
    const int tx = threadIdx.x, ty = threadIdx.y;
    #pragma unroll
    for (int j = 0; j < 4; j++)
        t[ty + 8 * j][tx] = s[(size_t)(r0 + ty + 8 * j) * C + c0 + tx];
    __syncthreads();
    #pragma unroll
    for (int j = 0; j < 4; j++) {
        const float v = t[tx][ty + 8 * j];
        const __nv_bfloat16 h = __float2bfloat16(v);
        const __nv_bfloat16 l = __float2bfloat16(v - __bfloat162float(h));
        const size_t o = pcs_off(c0 + ty + 8 * j, r0 + tx, R);
        *(__nv_bfloat16*)((char*)dh + o) = h;
        *(__nv_bfloat16*)((char*)dl + o) = l;
    }
}

// ---------------------------------------------------------------------------
// BatchNorm (training stats) + ReLU; fp32 h1 -> PCS bf16 hi/lo
// ---------------------------------------------------------------------------
__global__ void zero_stats()
{
    const int i = blockIdx.x * blockDim.x + threadIdx.x;
    if (i < H3) { g_sum[i] = 0.0; g_sq[i] = 0.0; }
}

__global__ void bn_stats(const float* __restrict__ h)
{
    const int col = blockIdx.x * 256 + threadIdx.x;
    const int r0 = blockIdx.y * 256;
    double ls = 0.0, lq = 0.0;
    #pragma unroll 4
    for (int r = r0; r < r0 + 256; r++) {
        const float v = h[(size_t)r * H3 + col];
        ls += (double)v;
        lq += (double)v * (double)v;
    }
    atomicAdd(&g_sum[col], ls);
    atomicAdd(&g_sq[col], lq);
}

__global__ void bn_apply_pcs(const float* __restrict__ h,
                             const float* __restrict__ gamma,
                             const float* __restrict__ beta,
                             __nv_bfloat16* __restrict__ oh,
                             __nv_bfloat16* __restrict__ ol)
{
    constexpr int K8 = H3 >> 3;
    const size_t i8 = (size_t)blockIdx.x * 256 + threadIdx.x;
    if (i8 >= (size_t)NNODE * K8) return;
    const int r = (int)(i8 / K8);
    const int k = (int)(i8 % K8) << 3;
    const float4 u0 = *(const float4*)(h + (size_t)r * H3 + k);
    const float4 u1 = *(const float4*)(h + (size_t)r * H3 + k + 4);
    const float a[8] = {u0.x, u0.y, u0.z, u0.w, u1.x, u1.y, u1.z, u1.w};
    __nv_bfloat16 hh[8], ll[8];
    #pragma unroll
    for (int q = 0; q < 8; q++) {
        const int col = k + q;
        const double mu = g_sum[col] / (double)NNODE;
        const double var = g_sq[col] / (double)NNODE - mu * mu;
        const float rstd = rsqrtf((float)var + BN_EPS);
        float v = (a[q] - (float)mu) * rstd * gamma[col] + beta[col];
        v = v > 0.0f ? v : 0.0f;
        hh[q] = __float2bfloat16(v);
        ll[q] = __float2bfloat16(v - __bfloat162float(hh[q]));
    }
    const size_t o = pcs_off(r, k, H3);
    __nv_bfloat162* ph = (__nv_bfloat162*)((char*)oh + o);
    __nv_bfloat162* pl = (__nv_bfloat162*)((char*)ol + o);
    #pragma unroll
    for (int q = 0; q < 4; q++) {
        ph[q] = __halves2bfloat162(hh[2 * q], hh[2 * q + 1]);
        pl[q] = __halves2bfloat162(ll[2 * q], ll[2 * q + 1]);
    }
}

// ---------------------------------------------------------------------------
// Orchestration
// ---------------------------------------------------------------------------
extern "C" void kernel_launch(void* const* d_in, const int* in_sizes, int n_in,
                              void* d_out, int out_size)
{
    const float* x     = (const float*)d_in[0];
    const float* adj   = (const float*)d_in[1];
    const float* W1    = (const float*)d_in[2];
    const float* b1    = (const float*)d_in[3];
    const float* W2    = (const float*)d_in[4];
    const float* b2    = (const float*)d_in[5];
    const float* gamma = (const float*)d_in[6];
    const float* beta  = (const float*)d_in[7];
    const float* Wf    = (const float*)d_in[8];
    const float* bf    = (const float*)d_in[9];
    float* out = (float*)d_out;

    __nv_bfloat16 *adj_h, *adj_l, *x_h, *x_l, *W1t_h, *W1t_l, *W2t_h, *W2t_l;
    __nv_bfloat16 *Wft_h, *Wft_l, *T12t_h, *T12t_l, *T3t_h, *T3t_l;
    __nv_bfloat16 *U12t_h, *U12t_l, *U3t_h, *U3t_l, *h1_h, *h1_l, *h2_h, *h2_l;
    float *h1;
    cudaGetSymbolAddress((void**)&adj_h, g_adj_h);
    cudaGetSymbolAddress((void**)&adj_l, g_adj_l);
    cudaGetSymbolAddress((void**)&x_h, g_x_h);
    cudaGetSymbolAddress((void**)&x_l, g_x_l);
    cudaGetSymbolAddress((void**)&W1t_h, g_W1t_h);
    cudaGetSymbolAddress((void**)&W1t_l, g_W1t_l);
    cudaGetSymbolAddress((void**)&W2t_h, g_W2t_h);
    cudaGetSymbolAddress((void**)&W2t_l, g_W2t_l);
    cudaGetSymbolAddress((void**)&Wft_h, g_Wft_h);
    cudaGetSymbolAddress((void**)&Wft_l, g_Wft_l);
    cudaGetSymbolAddress((void**)&T12t_h, g_T12t_h);
    cudaGetSymbolAddress((void**)&T12t_l, g_T12t_l);
    cudaGetSymbolAddress((void**)&T3t_h, g_T3t_h);
    cudaGetSymbolAddress((void**)&T3t_l, g_T3t_l);
    cudaGetSymbolAddress((void**)&U12t_h, g_U12t_h);
    cudaGetSymbolAddress((void**)&U12t_l, g_U12t_l);
    cudaGetSymbolAddress((void**)&U3t_h, g_U3t_h);
    cudaGetSymbolAddress((void**)&U3t_l, g_U3t_l);
    cudaGetSymbolAddress((void**)&h1_h, g_h1_h);
    cudaGetSymbolAddress((void**)&h1_l, g_h1_l);
    cudaGetSymbolAddress((void**)&h2_h, g_h2_h);
    cudaGetSymbolAddress((void**)&h2_l, g_h2_l);
    cudaGetSymbolAddress((void**)&h1, g_h1);

    constexpr int SMEM256 = 1024 + 4 * ((2 + 4) * 8192);  // 197632
    constexpr int SMEM128 = 1024 + 4 * ((2 + 2) * 8192);  // 132096
    cudaFuncSetAttribute(gemm_mma<256>, cudaFuncAttributeMaxDynamicSharedMemorySize, SMEM256);
    cudaFuncSetAttribute(gemm_mma<128>, cudaFuncAttributeMaxDynamicSharedMemorySize, SMEM128);

    const int NOSPLIT = 1 << 30;
    const dim3 blk(256);
    const int MB = NNODE / 128;   // 64

    // ---- input conversions (all into PCS) ----
    {
        const size_t n8x = (size_t)NNODE * IN_DIM / 8;
        cvt_split_pcs<<<(unsigned)((n8x + 255) / 256), 256>>>(x, x_h, x_l, NNODE, IN_DIM);
        const size_t n8a = (size_t)NNODE * NNODE / 8;
        cvt_split_pcs<<<(unsigned)((n8a + 255) / 256), 256>>>(adj, adj_h, adj_l, NNODE, NNODE);
    }
    for (int j = 0; j < 3; j++) {
        cvt_split_tr_pcs<<<dim3(HID / 32, IN_DIM / 32), dim3(32, 8)>>>(
            W1 + (size_t)j * IN_DIM * HID, W1t_h + (size_t)j * HID * IN_DIM,
            W1t_l + (size_t)j * HID * IN_DIM, IN_DIM, HID);
        cvt_split_tr_pcs<<<dim3(OUTD / 32, H3 / 32), dim3(32, 8)>>>(
            W2 + (size_t)j * H3 * OUTD, W2t_h + (size_t)j * OUTD * H3,
            W2t_l + (size_t)j * OUTD * H3, H3, OUTD);
    }
    cvt_split_tr_pcs<<<dim3(OUTD / 32, O3 / 32), dim3(32, 8)>>>(Wf, Wft_h, Wft_l, O3, OUTD);

    // ---- GEMM 1: x @ [W1_0|W1_1|W1_2]  (N=1536; <512 -> h1 fp32, >=512 -> T12^T) ----
    gemm_mma<256><<<dim3(6, MB), blk, SMEM256>>>(x_h, x_l, W1t_h, W1t_l, IN_DIM,
        h1, nullptr, nullptr, H3, 0, T12t_h, T12t_l, 512, b1);

    // ---- GEMM 2: adj @ [T1|T2]  (N=1024; <512 -> h1 hop1 fp32, >=512 -> T3^T) ----
    gemm_mma<256><<<dim3(4, MB), blk, SMEM256>>>(adj_h, adj_l, T12t_h, T12t_l, NNODE,
        h1 + HID, nullptr, nullptr, H3, 0, T3t_h, T3t_l, 512, nullptr);

    // ---- GEMM 3: adj @ T3  (N=512 -> h1 hop2 fp32) ----
    gemm_mma<256><<<dim3(2, MB), blk, SMEM256>>>(adj_h, adj_l, T3t_h, T3t_l, NNODE,
        h1 + 2 * HID, nullptr, nullptr, H3, 0, nullptr, nullptr, NOSPLIT, nullptr);

    // ---- BN + ReLU -> h1 PCS bf16 ----
    zero_stats<<<(H3 + 255) / 256, 256>>>();
    bn_stats<<<dim3(H3 / 256, NNODE / 256), 256>>>(h1);
    {
        const size_t n8 = (size_t)NNODE * H3 / 8;
        bn_apply_pcs<<<(unsigned)((n8 + 255) / 256), 256>>>(h1, gamma, beta, h1_h, h1_l);
    }

    // ---- GEMM 4: h1 @ [W2_0|W2_1|W2_2]  (N=768; <256 -> h2 PCS cols 0-255, >=256 -> U12^T) ----
    gemm_mma<256><<<dim3(3, MB), blk, SMEM256>>>(h1_h, h1_l, W2t_h, W2t_l, H3,
        nullptr, h2_h, h2_l, O3, 0, U12t_h, U12t_l, 256, b2);

    // ---- GEMM 5: adj @ [U1|U2]  (N=512; <256 -> h2 PCS cols 256-511, >=256 -> U3^T) ----
    gemm_mma<256><<<dim3(2, MB), blk, SMEM256>>>(adj_h, adj_l, U12t_h, U12t_l, NNODE,
        nullptr, h2_h, h2_l, O3, OUTD, U3t_h, U3t_l, 256, nullptr);

    // ---- GEMM 6: adj @ U3  (N=256 -> h2 PCS cols 512-767) ----
    gemm_mma<128><<<dim3(2, MB), blk, SMEM128>>>(adj_h, adj_l, U3t_h, U3t_l, NNODE,
        nullptr, h2_h, h2_l, O3, 2 * OUTD, nullptr, nullptr, NOSPLIT, nullptr);

    // ---- GEMM 7: out = h2 @ Wf + bf  (N=256, fp32) ----
    gemm_mma<128><<<dim3(2, MB), blk, SMEM128>>>(h2_h, h2_l, Wft_h, Wft_l, O3,
        out, nullptr, nullptr, OUTD, 0, nullptr, nullptr, NOSPLIT, bf);
}